// round 2
// baseline (speedup 1.0000x reference)
#include <cuda_runtime.h>
#include <cuda_bf16.h>

#define NT 48
#define SEQ 512
#define BATCH 1024
#define BPB 2                 // batches per block
#define THREADS (BPB * NT)    // 96 threads = 3 full warps

// Viterbi forward: one thread owns one (batch, tag_j) stream.
//   - T[:, j] column cached in 48 registers (persistent across all 511 steps)
//   - state vector shared per batch in SMEM, double buffered, 1 barrier/step
//   - 4 interleaved max chains for ILP; exact first-occurrence argmax tie-break
__global__ __launch_bounds__(THREADS, 4)
void crf_viterbi_kernel(const float* __restrict__ pot,
                        const float* __restrict__ trans,
                        float* __restrict__ out)
{
    __shared__ __align__(16) float st[2][BPB][NT];

    const int tid = threadIdx.x;
    const int lb  = tid / NT;        // local batch 0/1
    const int j   = tid - lb * NT;   // tag column
    const int b   = blockIdx.x * BPB + lb;

    // Cache transition column T[i][j] in registers (one-time strided load)
    float tc[NT];
#pragma unroll
    for (int i = 0; i < NT; i++) tc[i] = trans[i * NT + j];

    const float* potb = pot + (size_t)b * SEQ * NT + j;
    float* bpp        = out + (size_t)b * (SEQ - 1) * NT + j;
    float* scores     = out + (size_t)BATCH * (SEQ - 1) * NT;

    // init_state = potentials[:, 0]
    float ns = potb[0];
    st[0][lb][j] = ns;
    __syncthreads();

    // 2-deep prefetch of unary potentials with a running pointer (no per-step IMAD)
    const float* pp = potb + 3 * NT;   // next address to fetch (t = 3)
    float pn1 = potb[NT];              // t = 1
    float pn2 = potb[2 * NT];          // t = 2
    int buf = 0;

    for (int t = 1; t < SEQ; ++t) {
        const float p = pn1;
        pn1 = pn2;
        if (t + 2 <= SEQ - 1) { pn2 = *pp; pp += NT; }

        // Load the full 48-float state vector via 12x LDS.128 (broadcast within batch)
        float stt[NT];
        const float4* sp = (const float4*)st[buf][lb];
#pragma unroll
        for (int k = 0; k < NT / 4; k++) {
            float4 v = sp[k];
            stt[4 * k + 0] = v.x; stt[4 * k + 1] = v.y;
            stt[4 * k + 2] = v.z; stt[4 * k + 3] = v.w;
        }

        // 4 interleaved argmax chains (strict > ascending => first max per chain)
        float m0 = stt[0] + tc[0]; int i0 = 0;
        float m1 = stt[1] + tc[1]; int i1 = 1;
        float m2 = stt[2] + tc[2]; int i2 = 2;
        float m3 = stt[3] + tc[3]; int i3 = 3;
#pragma unroll
        for (int k = 1; k < NT / 4; k++) {
            const int base = 4 * k;
            float s;
            s = stt[base + 0] + tc[base + 0]; if (s > m0) { m0 = s; i0 = base + 0; }
            s = stt[base + 1] + tc[base + 1]; if (s > m1) { m1 = s; i1 = base + 1; }
            s = stt[base + 2] + tc[base + 2]; if (s > m2) { m2 = s; i2 = base + 2; }
            s = stt[base + 3] + tc[base + 3]; if (s > m3) { m3 = s; i3 = base + 3; }
        }
        // Merge chains; on exact float tie, the smaller index wins (jnp.argmax semantics)
        float mA; int iA;
        if (m1 > m0 || (m1 == m0 && i1 < i0)) { mA = m1; iA = i1; } else { mA = m0; iA = i0; }
        float mB; int iB;
        if (m3 > m2 || (m3 == m2 && i3 < i2)) { mB = m3; iB = i3; } else { mB = m2; iB = i2; }
        float m; int idx;
        if (mB > mA || (mB == mA && iB < iA)) { m = mB; idx = iB; } else { m = mA; idx = iA; }

        ns = p + m;                       // new_state (single FADD, bit-exact vs ref)
        st[buf ^ 1][lb][j] = ns;          // double-buffer write (prev readers synced)
        bpp[0] = (float)idx;
        bpp += NT;
        __syncthreads();
        buf ^= 1;
    }

    scores[(size_t)b * NT + j] = ns;
}

extern "C" void kernel_launch(void* const* d_in, const int* in_sizes, int n_in,
                              void* d_out, int out_size)
{
    const float* pot   = (const float*)d_in[0];
    const float* trans = (const float*)d_in[1];
    float* out         = (float*)d_out;
    crf_viterbi_kernel<<<BATCH / BPB, THREADS>>>(pot, trans, out);
}